// round 2
// baseline (speedup 1.0000x reference)
#include <cuda_runtime.h>

// SFAM_43490838839386: f = clip(tanh(x)/||tanh(x)||_2 + 0.01*noise, -1.5, 1.5)
//                      out = tanh(einsum('bi,bij->bj', f, P))
// B=4096, D=256, S=256, fp32. HBM-bound: P is 1.07 GB read once.

#define Dk 256
#define Sk 256
#define NOISE_STD 0.01f
#define EPSN 1e-12f

__global__ __launch_bounds__(256, 8)
void sfam_kernel(const float* __restrict__ raw,
                 const float* __restrict__ proj,
                 const float* __restrict__ noise,
                 float* __restrict__ out)
{
    __shared__ float f_sh[Dk];
    __shared__ float red[4 * Sk];
    __shared__ float warp_sums[8];

    const int b   = blockIdx.x;
    const int tid = threadIdx.x;

    // ---------------- Phase 1: build f[b, :] in shared ----------------
    const float t  = tanhf(raw[(size_t)b * Dk + tid]);
    float sq = t * t;
    #pragma unroll
    for (int o = 16; o > 0; o >>= 1)
        sq += __shfl_xor_sync(0xffffffffu, sq, o);
    const int lane = tid & 31;
    const int wid  = tid >> 5;
    if (lane == 0) warp_sums[wid] = sq;
    __syncthreads();
    if (tid < 8) {
        float v = warp_sums[tid];
        #pragma unroll
        for (int o = 4; o > 0; o >>= 1)
            v += __shfl_xor_sync(0xffu, v, o);
        if (tid == 0) warp_sums[0] = v;
    }
    __syncthreads();
    const float inv = 1.0f / fmaxf(sqrtf(warp_sums[0]), EPSN);

    float fv = fmaf(t, inv, NOISE_STD * noise[(size_t)b * Dk + tid]);
    fv = fminf(fmaxf(fv, -1.5f), 1.5f);
    f_sh[tid] = fv;
    __syncthreads();

    // ---------------- Phase 2: hashed[j] = sum_i f[i] * P[b,i,j] ----------------
    // 64 column-groups (float4 each) x 4 i-slices. Each thread streams 64 rows'
    // worth of one float4 column chunk -> fully coalesced 1KB/row per 64 threads.
    const int jg     = tid & 63;   // column group: columns 4*jg .. 4*jg+3
    const int islice = tid >> 6;   // 0..3

    const float* pbase = proj + (size_t)b * Dk * Sk + (size_t)jg * 4;
    float4 acc = make_float4(0.f, 0.f, 0.f, 0.f);

    #pragma unroll 8
    for (int i = islice; i < Dk; i += 4) {
        const float  fi = f_sh[i];
        const float4 p  = *reinterpret_cast<const float4*>(pbase + (size_t)i * Sk);
        acc.x = fmaf(fi, p.x, acc.x);
        acc.y = fmaf(fi, p.y, acc.y);
        acc.z = fmaf(fi, p.z, acc.z);
        acc.w = fmaf(fi, p.w, acc.w);
    }

    *reinterpret_cast<float4*>(&red[islice * Sk + jg * 4]) = acc;
    __syncthreads();

    // Reduce 4 slices for column tid, final tanh, store.
    const float h = red[tid] + red[Sk + tid] + red[2 * Sk + tid] + red[3 * Sk + tid];
    out[(size_t)b * Sk + tid] = tanhf(h);
}

extern "C" void kernel_launch(void* const* d_in, const int* in_sizes, int n_in,
                              void* d_out, int out_size)
{
    const float* raw   = (const float*)d_in[0];
    const float* proj  = (const float*)d_in[1];
    const float* noise = (const float*)d_in[2];
    float* out = (float*)d_out;

    const int B = in_sizes[0] / Dk;  // 4096
    sfam_kernel<<<B, 256>>>(raw, proj, noise, out);
}

// round 3
// speedup vs baseline: 1.0393x; 1.0393x over previous
#include <cuda_runtime.h>

// SFAM_43490838839386: f = clip(tanh(x)/||tanh(x)||_2 + 0.01*noise, -1.5, 1.5)
//                      out = tanh(einsum('bi,bij->bj', f, P))
// B=4096, D=256, S=256, fp32. HBM-bound: P = 1.07 GB read once.
// R2: 2 CTAs per sample (128 cols each) -> 8192 CTAs, 92%-full last wave;
//     __ldcs streaming loads on P (read-once, keep out of L2).

#define Dk 256
#define Sk 256
#define NOISE_STD 0.01f
#define EPSN 1e-12f

__global__ __launch_bounds__(256, 8)
void sfam_kernel(const float* __restrict__ raw,
                 const float* __restrict__ proj,
                 const float* __restrict__ noise,
                 float* __restrict__ out)
{
    __shared__ float f_sh[Dk];
    __shared__ float red[8 * 128];
    __shared__ float warp_sums[8];

    const int b    = blockIdx.x >> 1;   // sample
    const int half = blockIdx.x & 1;    // which 128-column half
    const int tid  = threadIdx.x;

    // ---------------- Phase 1: build f[b, :] in shared (duplicated per half) ----
    const float t = tanhf(raw[(size_t)b * Dk + tid]);
    float sq = t * t;
    #pragma unroll
    for (int o = 16; o > 0; o >>= 1)
        sq += __shfl_xor_sync(0xffffffffu, sq, o);
    const int lane = tid & 31;
    const int wid  = tid >> 5;
    if (lane == 0) warp_sums[wid] = sq;
    __syncthreads();
    if (tid < 8) {
        float v = warp_sums[tid];
        #pragma unroll
        for (int o = 4; o > 0; o >>= 1)
            v += __shfl_xor_sync(0xffu, v, o);
        if (tid == 0) warp_sums[0] = v;
    }
    __syncthreads();
    const float inv = 1.0f / fmaxf(sqrtf(warp_sums[0]), EPSN);

    float fv = fmaf(t, inv, NOISE_STD * noise[(size_t)b * Dk + tid]);
    fv = fminf(fmaxf(fv, -1.5f), 1.5f);
    f_sh[tid] = fv;
    __syncthreads();

    // ---------------- Phase 2: hashed[j] = sum_i f[i] * P[b,i,j], j in this half --
    // 32 column-groups (float4) x 8 i-slices. Warp = one i-slice, lanes cover
    // 32*16B = 512B contiguous per row -> fully coalesced.
    const int jg     = tid & 31;   // columns half*128 + 4*jg .. +3
    const int islice = tid >> 5;   // 0..7

    const float* pbase = proj + (size_t)b * Dk * Sk + (size_t)half * 128 + (size_t)jg * 4;
    float4 acc = make_float4(0.f, 0.f, 0.f, 0.f);

    #pragma unroll 8
    for (int i = islice; i < Dk; i += 8) {
        const float  fi = f_sh[i];
        const float4 p  = __ldcs(reinterpret_cast<const float4*>(pbase + (size_t)i * Sk));
        acc.x = fmaf(fi, p.x, acc.x);
        acc.y = fmaf(fi, p.y, acc.y);
        acc.z = fmaf(fi, p.z, acc.z);
        acc.w = fmaf(fi, p.w, acc.w);
    }

    *reinterpret_cast<float4*>(&red[islice * 128 + jg * 4]) = acc;
    __syncthreads();

    // Reduce 8 slices for each of the 128 columns, final tanh, store.
    if (tid < 128) {
        float h = 0.f;
        #pragma unroll
        for (int s = 0; s < 8; s++) h += red[s * 128 + tid];
        out[(size_t)b * Sk + (size_t)half * 128 + tid] = tanhf(h);
    }
}

extern "C" void kernel_launch(void* const* d_in, const int* in_sizes, int n_in,
                              void* d_out, int out_size)
{
    const float* raw   = (const float*)d_in[0];
    const float* proj  = (const float*)d_in[1];
    const float* noise = (const float*)d_in[2];
    float* out = (float*)d_out;

    const int B = in_sizes[0] / Dk;  // 4096
    sfam_kernel<<<2 * B, 256>>>(raw, proj, noise, out);
}